// round 15
// baseline (speedup 1.0000x reference)
#include <cuda_runtime.h>

#define G       180
#define NA      64
#define Bx      27
#define RMAX    13
#define SPLIT   2
#define THREADS 384
#define NWARP   (THREADS/32)     // 12
#define AH      0.2f
#define ROF     2.5f
#define RO2F    6.25f
#define VCELLF  0.008f
#define NCOL    (Bx*Bx)          // 729
#define ROWS    (NWARP*16)       // 192 staged rows
#define RSTR    136              // padded row stride (floats), 16B aligned
#define DSMEM   (ROWS*RSTR*4)    // 104448 bytes

__device__ float        g_partial[NA * SPLIT * 128];
__device__ unsigned int g_count[NA];

typedef unsigned long long u64;

__device__ __forceinline__ u64 pk2(float lo, float hi) {
    u64 r; asm("mov.b64 %0, {%1, %2};" : "=l"(r) : "f"(lo), "f"(hi)); return r;
}
__device__ __forceinline__ void upk2(float& lo, float& hi, u64 v) {
    asm("mov.b64 {%0, %1}, %2;" : "=f"(lo), "=f"(hi) : "l"(v));
}
__device__ __forceinline__ void fma2(u64& d, u64 a, u64 b) {
    asm("fma.rn.f32x2 %0, %1, %2, %0;" : "+l"(d) : "l"(a), "l"(b));
}
__device__ __forceinline__ u64 mul2(u64 a, u64 b) {
    u64 r; asm("mul.rn.f32x2 %0, %1, %2;" : "=l"(r) : "l"(a), "l"(b)); return r;
}

extern __shared__ float dynbuf[];   // ROWS x RSTR floats

__device__ __forceinline__ void ring_ij(int cc, int& i, int& j)
{
    const float rf = sqrtf((float)cc);
    const int rr = (int)((rf + 1.0f) * 0.5f);      // square-ring index
    if (rr == 0) { i = RMAX; j = RMAX; return; }
    const int t    = cc - (2*rr - 1) * (2*rr - 1);
    const int side = t / (2*rr);
    const int posn = t - side * (2*rr);
    if      (side == 0) { i = RMAX - rr;        j = RMAX - rr + posn; }
    else if (side == 1) { i = RMAX - rr + posn; j = RMAX + rr; }
    else if (side == 2) { i = RMAX + rr;        j = RMAX + rr - posn; }
    else                { i = RMAX + rr - posn; j = RMAX - rr; }
}

__device__ __forceinline__ void cell_update(u64* c2a,
                                            float x, float y, float z,
                                            float c2d, float srho)
{
    const float r2  = fmaf(z, z, c2d);
    const float inv = rsqrtf(fmaxf(r2, 1e-24f));
    const float r   = r2 * inv;
    const float u   = fmaxf(ROF - r, 0.0f);    // zero outside cutoff
    const float p0  = r2 * u * u * srho;
    const float xh = x * inv, yh = y * inv, zh = z * inv;
    const float xh2 = xh*xh, yh2 = yh*yh, zh2 = zh*zh;

    u64 yp[8];
    {
        const float Y0  = 0.28209479177387814f;
        const float Y1  = 0.4886025119029199f * yh;
        const float Y2  = 0.4886025119029199f * zh;
        const float Y3  = 0.4886025119029199f * xh;
        const float Y4  = 1.0925484305920792f * xh * yh;
        const float Y5  = 1.0925484305920792f * yh * zh;
        const float Y6  = 0.31539156525252005f * (3.0f * zh2 - 1.0f);
        const float Y7  = 1.0925484305920792f * xh * zh;
        const float Y8  = 0.5462742152960396f * (xh2 - yh2);
        const float Y9  = 0.5900435899266435f * yh * (3.0f * xh2 - yh2);
        const float Y10 = 2.890611442640554f  * xh * yh * zh;
        const float Y11 = 0.4570457994644658f * yh * (5.0f * zh2 - 1.0f);
        const float Y12 = 0.3731763325901154f * zh * (5.0f * zh2 - 3.0f);
        const float Y13 = 0.4570457994644658f * xh * (5.0f * zh2 - 1.0f);
        const float Y14 = 1.445305721320277f  * zh * (xh2 - yh2);
        const float Y15 = 0.5900435899266435f * xh * (xh2 - 3.0f * yh2);
        yp[0] = pk2(Y0,  Y1);  yp[1] = pk2(Y2,  Y3);
        yp[2] = pk2(Y4,  Y5);  yp[3] = pk2(Y6,  Y7);
        yp[4] = pk2(Y8,  Y9);  yp[5] = pk2(Y10, Y11);
        yp[6] = pk2(Y12, Y13); yp[7] = pk2(Y14, Y15);
    }

    u64 tp = pk2(p0, p0);
    const u64 up = pk2(u, u);
    #pragma unroll
    for (int m = 0; m < 8; m++) {
        #pragma unroll
        for (int q = 0; q < 8; q++)
            fma2(c2a[m*8 + q], tp, yp[q]);
        if (m < 7) tp = mul2(tp, up);
    }
}

__device__ __forceinline__ void do_column(u64* c2a, const float2* ztab,
                                          const float* __restrict__ rho,
                                          int rowbase, float x, float y,
                                          float c2d, int klo, int khi)
{
    if (klo > khi) return;

    float2 zz0 = ztab[klo];
    float2 zz1 = ztab[min(klo + 1, 31)];
    float  sr0 = __ldg(rho + rowbase + __float_as_int(zz0.y));
    float  sr1 = __ldg(rho + rowbase + __float_as_int(zz1.y));

    #pragma unroll 1
    for (int k = klo; k <= khi; k += 2) {
        const int k2 = min(k + 2, 31);
        const int k3 = min(k + 3, 31);
        float2 nz0 = ztab[k2];
        float2 nz1 = ztab[k3];
        float  nr0 = __ldg(rho + rowbase + __float_as_int(nz0.y));
        float  nr1 = __ldg(rho + rowbase + __float_as_int(nz1.y));

        cell_update(c2a, x, y, zz0.x, c2d, sr0);
        const float m1 = (k + 1 <= khi) ? 1.0f : 0.0f;
        cell_update(c2a, x, y, zz1.x, c2d, sr1 * m1);

        zz0 = nz0;  zz1 = nz1;  sr0 = nr0;  sr1 = nr1;
    }
}

__global__ __launch_bounds__(THREADS)
void proj_kernel(const float* __restrict__ rho, const float* __restrict__ pos,
                 const float* __restrict__ W, float* __restrict__ out)
{
    const int blk  = blockIdx.x;
    const int atom = blk >> 1;          // SPLIT = 2 (chord halves)
    const int part = blk & 1;
    const int tid  = threadIdx.x;

    __shared__ float2 ztab[32];         // { z, zindex(asfloat) }, padded
    __shared__ float  spart[3 * 128];
    __shared__ unsigned int slast;

    const float px = pos[atom*3+0];
    const float py = pos[atom*3+1];
    const float pz = pos[atom*3+2];
    const float cmx = rintf(px * 5.0f);
    const float cmy = rintf(py * 5.0f);
    const float cmz = rintf(pz * 5.0f);
    const int cx = (int)cmx, cy = (int)cmy, cz = (int)cmz;
    const float dx = px - AH * cmx;
    const float dy = py - AH * cmy;
    const float dz = pz - AH * cmz;

    if (tid < 32) {
        const int kk = min(tid, Bx - 1);          // pad 27..31 with k=26
        int vz = cz + (kk - RMAX);
        vz += (vz < 0) ? G : 0;  vz -= (vz >= G) ? G : 0;
        const float zs = (float)(kk - RMAX) * AH - dz;
        ztab[tid] = make_float2(zs, __int_as_float(vz));
    }
    __syncthreads();

    // ---- chord-balanced pairing: thread t owns ring-ranks t and 728-t ----
    const bool actA = (tid < (NCOL + 1) / 2);            // t <= 364
    const int  ccA  = actA ? tid : 0;
    const int  ccB  = NCOL - 1 - ccA;                    // 728 - t
    const bool actB = actA && (ccB != ccA);

    // packed accumulators: c2a[m*8+p] = (coef[m][2p], coef[m][2p+1])
    u64 c2a[64];
    #pragma unroll
    for (int v = 0; v < 64; v++) c2a[v] = 0ull;

    #pragma unroll
    for (int side = 0; side < 2; side++) {
        const bool act = side ? actB : actA;
        const int  cc  = side ? ccB : ccA;

        int i, j;
        ring_ij(cc, i, j);
        const int di = i - RMAX, dj = j - RMAX;
        int vx = cx + di;  vx += (vx < 0) ? G : 0;  vx -= (vx >= G) ? G : 0;
        int vy = cy + dj;  vy += (vy < 0) ? G : 0;  vy -= (vy >= G) ? G : 0;
        const int rowbase = (vx * G + vy) * G;
        const float x   = (float)di * AH - dx;
        const float y   = (float)dj * AH - dy;
        const float c2d = x * x + y * y;
        const float s2  = RO2F - c2d;

        // EXACT chord bounds (cells outside have u = 0 → contribution 0)
        int k0 = 1, k1 = 0;
        if (act && s2 > 0.0f) {
            const float sq = sqrtf(s2);
            k0 = max(0,  (int)ceilf (13.0f + (dz - sq) * 5.0f));
            k1 = min(26, (int)floorf(13.0f + (dz + sq) * 5.0f));
        }

        // split this chord between the atom's two blocks
        const int n    = k1 - k0 + 1;
        const int half = (n + 1) >> 1;          // ceil(n/2)
        int klo, khi;
        if (part == 0) { klo = k0;        khi = k0 + half - 1; }
        else           { klo = k0 + half; khi = k1; }

        do_column(c2a, ztab, rho, rowbase, x, y, c2d, klo, khi);
    }

    // ---- one shfl fold (32 -> 16 lanes) ----
    const int lane = tid & 31, warp = tid >> 5;
    #pragma unroll
    for (int v = 0; v < 64; v++) {
        float lo, hi;
        upk2(lo, hi, c2a[v]);
        lo += __shfl_down_sync(0xffffffffu, lo, 16);
        hi += __shfl_down_sync(0xffffffffu, hi, 16);
        c2a[v] = pk2(lo, hi);
    }

    // ---- stage 192 rows x 128 floats to dynamic smem ----
    if (lane < 16) {
        float* dst = dynbuf + (warp * 16 + lane) * RSTR;
        #pragma unroll
        for (int v = 0; v < 64; v += 2)
            *reinterpret_cast<ulonglong2*>(dst + 2 * v) =
                make_ulonglong2(c2a[v], c2a[v + 1]);
    }
    __syncthreads();

    // ---- flat reduce: 3 threads per value, 64 rows each,
    //      8 interleaved stripes + pairwise combine (tree-like rounding) ----
    {
        const int v   = tid & 127;
        const int seg = tid >> 7;            // 0..2
        const float* src = dynbuf + (seg * 64) * RSTR + v;
        float a0=0,a1=0,a2=0,a3=0,a4=0,a5=0,a6=0,a7=0;
        #pragma unroll
        for (int r = 0; r < 64; r += 8) {
            a0 += src[(r+0) * RSTR];
            a1 += src[(r+1) * RSTR];
            a2 += src[(r+2) * RSTR];
            a3 += src[(r+3) * RSTR];
            a4 += src[(r+4) * RSTR];
            a5 += src[(r+5) * RSTR];
            a6 += src[(r+6) * RSTR];
            a7 += src[(r+7) * RSTR];
        }
        spart[seg * 128 + v] = ((a0 + a1) + (a2 + a3)) + ((a4 + a5) + (a6 + a7));
    }
    __syncthreads();

    if (tid < 128) {
        const float s = (spart[tid] + spart[128 + tid]) + spart[256 + tid];
        g_partial[blk * 128 + tid] = s;
    }
    __threadfence();
    __syncthreads();

    if (tid == 0) {
        const unsigned int ticket = atomicAdd(&g_count[atom], 1u);
        slast = (ticket == SPLIT - 1) ? 1u : 0u;
    }
    __syncthreads();

    if (slast) {
        const volatile float* gp = g_partial;
        if (tid < 128) {
            float s = 0.0f;
            #pragma unroll
            for (int p = 0; p < SPLIT; p++)
                s += gp[(atom * SPLIT + p) * 128 + tid];
            spart[tid] = s;
        }
        __syncthreads();
        if (tid < 128) {
            const int n = tid >> 4;
            const int q = tid & 15;
            float o = 0.0f;
            #pragma unroll
            for (int m = 0; m < 8; m++)
                o = fmaf(W[n * 8 + m], spart[m * 16 + q], o);
            out[atom * 128 + tid] = o * VCELLF;
        }
        if (tid == 0) g_count[atom] = 0u;
    }
}

extern "C" void kernel_launch(void* const* d_in, const int* in_sizes, int n_in,
                              void* d_out, int out_size)
{
    const float* rho = (const float*)d_in[0];   // 180^3
    const float* pos = (const float*)d_in[1];   // 64 x 3
    const float* W   = (const float*)d_in[2];   // 8 x 8
    float* out = (float*)d_out;                 // 64 x 128

    cudaFuncSetAttribute(proj_kernel,
                         cudaFuncAttributeMaxDynamicSharedMemorySize, DSMEM);
    proj_kernel<<<NA * SPLIT, THREADS, DSMEM>>>(rho, pos, W, out);
}

// round 17
// speedup vs baseline: 1.4855x; 1.4855x over previous
#include <cuda_runtime.h>

#define G       180
#define NA      64
#define Bx      27
#define RMAX    13
#define SPLIT   2
#define THREADS 384
#define NWARP   (THREADS/32)     // 12
#define AH      0.2f
#define ROF     2.5f
#define RO2F    6.25f
#define VCELLF  0.008f
#define NCOL    (Bx*Bx)          // 729
#define ROWS    (NWARP*16)       // 192 staged rows
#define RSTR    136              // padded row stride (floats), 16B aligned
#define DSMEM   (ROWS*RSTR*4)    // 104448 bytes

__device__ float        g_partial[NA * SPLIT * 128];
__device__ unsigned int g_count[NA];

typedef unsigned long long u64;

__device__ __forceinline__ u64 pk2(float lo, float hi) {
    u64 r; asm("mov.b64 %0, {%1, %2};" : "=l"(r) : "f"(lo), "f"(hi)); return r;
}
__device__ __forceinline__ void upk2(float& lo, float& hi, u64 v) {
    asm("mov.b64 {%0, %1}, %2;" : "=f"(lo), "=f"(hi) : "l"(v));
}
__device__ __forceinline__ void fma2(u64& d, u64 a, u64 b) {
    asm("fma.rn.f32x2 %0, %1, %2, %0;" : "+l"(d) : "l"(a), "l"(b));
}
__device__ __forceinline__ u64 mul2(u64 a, u64 b) {
    u64 r; asm("mul.rn.f32x2 %0, %1, %2;" : "=l"(r) : "l"(a), "l"(b)); return r;
}

extern __shared__ float dynbuf[];   // ROWS x RSTR floats

__device__ __forceinline__ void cell_update(u64* c2a,
                                            float x, float y, float z,
                                            float c2d, float srho)
{
    const float r2  = fmaf(z, z, c2d);
    const float inv = rsqrtf(fmaxf(r2, 1e-24f));
    const float r   = r2 * inv;
    const float u   = fmaxf(ROF - r, 0.0f);    // zero outside cutoff
    const float p0  = r2 * u * u * srho;
    const float xh = x * inv, yh = y * inv, zh = z * inv;
    const float xh2 = xh*xh, yh2 = yh*yh, zh2 = zh*zh;

    u64 yp[8];
    {
        const float Y0  = 0.28209479177387814f;
        const float Y1  = 0.4886025119029199f * yh;
        const float Y2  = 0.4886025119029199f * zh;
        const float Y3  = 0.4886025119029199f * xh;
        const float Y4  = 1.0925484305920792f * xh * yh;
        const float Y5  = 1.0925484305920792f * yh * zh;
        const float Y6  = 0.31539156525252005f * (3.0f * zh2 - 1.0f);
        const float Y7  = 1.0925484305920792f * xh * zh;
        const float Y8  = 0.5462742152960396f * (xh2 - yh2);
        const float Y9  = 0.5900435899266435f * yh * (3.0f * xh2 - yh2);
        const float Y10 = 2.890611442640554f  * xh * yh * zh;
        const float Y11 = 0.4570457994644658f * yh * (5.0f * zh2 - 1.0f);
        const float Y12 = 0.3731763325901154f * zh * (5.0f * zh2 - 3.0f);
        const float Y13 = 0.4570457994644658f * xh * (5.0f * zh2 - 1.0f);
        const float Y14 = 1.445305721320277f  * zh * (xh2 - yh2);
        const float Y15 = 0.5900435899266435f * xh * (xh2 - 3.0f * yh2);
        yp[0] = pk2(Y0,  Y1);  yp[1] = pk2(Y2,  Y3);
        yp[2] = pk2(Y4,  Y5);  yp[3] = pk2(Y6,  Y7);
        yp[4] = pk2(Y8,  Y9);  yp[5] = pk2(Y10, Y11);
        yp[6] = pk2(Y12, Y13); yp[7] = pk2(Y14, Y15);
    }

    u64 tp = pk2(p0, p0);
    const u64 up = pk2(u, u);
    #pragma unroll
    for (int m = 0; m < 8; m++) {
        #pragma unroll
        for (int q = 0; q < 8; q++)
            fma2(c2a[m*8 + q], tp, yp[q]);
        if (m < 7) tp = mul2(tp, up);
    }
}

__global__ __launch_bounds__(THREADS)
void proj_kernel(const float* __restrict__ rho, const float* __restrict__ pos,
                 const float* __restrict__ W, float* __restrict__ out)
{
    const int blk  = blockIdx.x;
    const int atom = blk >> 1;          // SPLIT = 2 (column parity)
    const int part = blk & 1;
    const int tid  = threadIdx.x;
    const int lane = tid & 31, warp = tid >> 5;

    __shared__ float2 ztab[32];         // { z, zindex(asfloat) }, padded
    __shared__ float  spart[3 * 128];
    __shared__ unsigned int slast;

    const float px = pos[atom*3+0];
    const float py = pos[atom*3+1];
    const float pz = pos[atom*3+2];
    const float cmx = rintf(px * 5.0f);
    const float cmy = rintf(py * 5.0f);
    const float cmz = rintf(pz * 5.0f);
    const int cx = (int)cmx, cy = (int)cmy, cz = (int)cmz;
    const float dx = px - AH * cmx;
    const float dy = py - AH * cmy;
    const float dz = pz - AH * cmz;

    if (tid < 32) {
        const int kk = min(tid, Bx - 1);          // pad 27..31 with k=26
        int vz = cz + (kk - RMAX);
        vz += (vz < 0) ? G : 0;  vz -= (vz >= G) ? G : 0;
        const float zs = (float)(kk - RMAX) * AH - dz;
        ztab[tid] = make_float2(zs, __int_as_float(vz));
    }
    __syncthreads();

    // ---- SMSP-balanced chunk permutation: warp w takes ring-chunk P(w).
    // SMSP s holds warps {s, s+4, s+8}; P pairs long chunks with short ones
    // so the per-SMSP work sums are nearly equal.
    const int pw   = (warp < 4) ? warp : ((warp < 8) ? (11 - warp) : warp);
    const int rank = pw * 32 + lane;                 // ring rank within parity set
    const int cidx = 2 * rank + part;
    const bool activ = (cidx < NCOL);
    const int cc     = activ ? cidx : 0;

    int i, j;
    {
        const float rf = sqrtf((float)cc);
        const int rr = (int)((rf + 1.0f) * 0.5f);      // square-ring index
        if (rr == 0) { i = RMAX; j = RMAX; }
        else {
            const int t    = cc - (2*rr - 1) * (2*rr - 1);
            const int side = t / (2*rr);
            const int posn = t - side * (2*rr);
            if      (side == 0) { i = RMAX - rr;        j = RMAX - rr + posn; }
            else if (side == 1) { i = RMAX - rr + posn; j = RMAX + rr; }
            else if (side == 2) { i = RMAX + rr;        j = RMAX + rr - posn; }
            else                { i = RMAX + rr - posn; j = RMAX - rr; }
        }
    }

    // ---- per-column constants ----
    const int di = i - RMAX, dj = j - RMAX;
    int vx = cx + di;  vx += (vx < 0) ? G : 0;  vx -= (vx >= G) ? G : 0;
    int vy = cy + dj;  vy += (vy < 0) ? G : 0;  vy -= (vy >= G) ? G : 0;
    const int rowbase = (vx * G + vy) * G;
    const float x   = (float)di * AH - dx;
    const float y   = (float)dj * AH - dy;
    const float c2d = x * x + y * y;
    const float s2  = RO2F - c2d;

    // EXACT chord bounds: cells outside [kmin,kmax] have u = 0 (contribution 0)
    int kmin = 1, kmax = 0;
    if (activ && s2 > 0.0f) {
        const float sq = sqrtf(s2);
        kmin = max(0,  (int)ceilf (13.0f + (dz - sq) * 5.0f));
        kmax = min(26, (int)floorf(13.0f + (dz + sq) * 5.0f));
    }

    // packed accumulators: c2a[m*8+p] = (coef[m][2p], coef[m][2p+1])
    u64 c2a[64];
    #pragma unroll
    for (int v = 0; v < 64; v++) c2a[v] = 0ull;

    if (kmin <= kmax) {
        // distance-2 rolling prefetch (ztab padded so indices never branch)
        float2 zz0 = ztab[kmin];
        float2 zz1 = ztab[min(kmin + 1, 31)];
        float  sr0 = __ldg(rho + rowbase + __float_as_int(zz0.y));
        float  sr1 = __ldg(rho + rowbase + __float_as_int(zz1.y));

        #pragma unroll 1
        for (int k = kmin; k <= kmax; k += 2) {
            const int k2 = min(k + 2, 31);
            const int k3 = min(k + 3, 31);
            float2 nz0 = ztab[k2];
            float2 nz1 = ztab[k3];
            float  nr0 = __ldg(rho + rowbase + __float_as_int(nz0.y));
            float  nr1 = __ldg(rho + rowbase + __float_as_int(nz1.y));

            cell_update(c2a, x, y, zz0.x, c2d, sr0);
            const float m1 = (k + 1 <= kmax) ? 1.0f : 0.0f;
            cell_update(c2a, x, y, zz1.x, c2d, sr1 * m1);

            zz0 = nz0;  zz1 = nz1;  sr0 = nr0;  sr1 = nr1;
        }
    }

    // ---- one shfl fold (32 -> 16 lanes) ----
    #pragma unroll
    for (int v = 0; v < 64; v++) {
        float lo, hi;
        upk2(lo, hi, c2a[v]);
        lo += __shfl_down_sync(0xffffffffu, lo, 16);
        hi += __shfl_down_sync(0xffffffffu, hi, 16);
        c2a[v] = pk2(lo, hi);
    }

    // ---- stage 192 rows x 128 floats to dynamic smem ----
    if (lane < 16) {
        float* dst = dynbuf + (warp * 16 + lane) * RSTR;
        #pragma unroll
        for (int v = 0; v < 64; v += 2)
            *reinterpret_cast<ulonglong2*>(dst + 2 * v) =
                make_ulonglong2(c2a[v], c2a[v + 1]);
    }
    __syncthreads();

    // ---- flat reduce: 3 threads per value, 64 rows each,
    //      8 interleaved stripes + pairwise combine (tree-like rounding) ----
    {
        const int v   = tid & 127;
        const int seg = tid >> 7;            // 0..2
        const float* src = dynbuf + (seg * 64) * RSTR + v;
        float a0=0,a1=0,a2=0,a3=0,a4=0,a5=0,a6=0,a7=0;
        #pragma unroll
        for (int r = 0; r < 64; r += 8) {
            a0 += src[(r+0) * RSTR];
            a1 += src[(r+1) * RSTR];
            a2 += src[(r+2) * RSTR];
            a3 += src[(r+3) * RSTR];
            a4 += src[(r+4) * RSTR];
            a5 += src[(r+5) * RSTR];
            a6 += src[(r+6) * RSTR];
            a7 += src[(r+7) * RSTR];
        }
        spart[seg * 128 + v] = ((a0 + a1) + (a2 + a3)) + ((a4 + a5) + (a6 + a7));
    }
    __syncthreads();

    if (tid < 128) {
        const float s = (spart[tid] + spart[128 + tid]) + spart[256 + tid];
        g_partial[blk * 128 + tid] = s;
    }
    __threadfence();
    __syncthreads();

    if (tid == 0) {
        const unsigned int ticket = atomicAdd(&g_count[atom], 1u);
        slast = (ticket == SPLIT - 1) ? 1u : 0u;
    }
    __syncthreads();

    if (slast) {
        const volatile float* gp = g_partial;
        if (tid < 128) {
            float s = 0.0f;
            #pragma unroll
            for (int p = 0; p < SPLIT; p++)
                s += gp[(atom * SPLIT + p) * 128 + tid];
            spart[tid] = s;
        }
        __syncthreads();
        if (tid < 128) {
            const int n = tid >> 4;
            const int q = tid & 15;
            float o = 0.0f;
            #pragma unroll
            for (int m = 0; m < 8; m++)
                o = fmaf(W[n * 8 + m], spart[m * 16 + q], o);
            out[atom * 128 + tid] = o * VCELLF;
        }
        if (tid == 0) g_count[atom] = 0u;
    }
}

extern "C" void kernel_launch(void* const* d_in, const int* in_sizes, int n_in,
                              void* d_out, int out_size)
{
    const float* rho = (const float*)d_in[0];   // 180^3
    const float* pos = (const float*)d_in[1];   // 64 x 3
    const float* W   = (const float*)d_in[2];   // 8 x 8
    float* out = (float*)d_out;                 // 64 x 128

    cudaFuncSetAttribute(proj_kernel,
                         cudaFuncAttributeMaxDynamicSharedMemorySize, DSMEM);
    proj_kernel<<<NA * SPLIT, THREADS, DSMEM>>>(rho, pos, W, out);
}